// round 2
// baseline (speedup 1.0000x reference)
#include <cuda_runtime.h>

// DCN CrossLayer: xl_{l+1} = x0 * dot(xl, w_l) + b_l + xl, 3 layers.
// B=16384 rows, F=1024 features. Warp-per-row, everything in registers.
// Inputs (metadata order): x [B,F] f32, kernels [3,F,1] f32, bias [3,F,1] f32.
// Output: [B,F] f32.

#define F_DIM 1024
#define VEC_PER_LANE 8   // 1024 floats / 32 lanes / 4 (float4)

__global__ void __launch_bounds__(256, 3)
cross_layer_kernel(const float4* __restrict__ x,
                   const float*  __restrict__ w,   // [3,1024]
                   const float*  __restrict__ b,   // [3,1024]
                   float4* __restrict__ out,
                   int n_rows)
{
    const int gwarp = (blockIdx.x * blockDim.x + threadIdx.x) >> 5;
    if (gwarp >= n_rows) return;
    const int lane = threadIdx.x & 31;

    const float4* __restrict__ xrow = x + (size_t)gwarp * (F_DIM / 4);

    float4 x0[VEC_PER_LANE];
    float4 xl[VEC_PER_LANE];

    // Front-batched coalesced loads: lane-contiguous float4s, stride 32 per chunk.
#pragma unroll
    for (int i = 0; i < VEC_PER_LANE; i++) {
        x0[i] = __ldg(&xrow[i * 32 + lane]);
        xl[i] = x0[i];
    }

#pragma unroll
    for (int l = 0; l < 3; l++) {
        const float4* __restrict__ wl = (const float4*)(w + l * F_DIM);
        const float4* __restrict__ bl = (const float4*)(b + l * F_DIM);

        // Per-lane partial dot over 32 elements (8 float4s).
        float s = 0.0f;
#pragma unroll
        for (int i = 0; i < VEC_PER_LANE; i++) {
            float4 wv = __ldg(&wl[i * 32 + lane]);
            s = fmaf(xl[i].x, wv.x, s);
            s = fmaf(xl[i].y, wv.y, s);
            s = fmaf(xl[i].z, wv.z, s);
            s = fmaf(xl[i].w, wv.w, s);
        }
        // Warp butterfly reduction -> full dot in every lane.
#pragma unroll
        for (int o = 16; o; o >>= 1)
            s += __shfl_xor_sync(0xffffffffu, s, o);

        // xl = x0 * s + b + xl
#pragma unroll
        for (int i = 0; i < VEC_PER_LANE; i++) {
            float4 bv = __ldg(&bl[i * 32 + lane]);
            xl[i].x = fmaf(x0[i].x, s, bv.x + xl[i].x);
            xl[i].y = fmaf(x0[i].y, s, bv.y + xl[i].y);
            xl[i].z = fmaf(x0[i].z, s, bv.z + xl[i].z);
            xl[i].w = fmaf(x0[i].w, s, bv.w + xl[i].w);
        }
    }

    float4* __restrict__ orow = out + (size_t)gwarp * (F_DIM / 4);
#pragma unroll
    for (int i = 0; i < VEC_PER_LANE; i++)
        orow[i * 32 + lane] = xl[i];
}

extern "C" void kernel_launch(void* const* d_in, const int* in_sizes, int n_in,
                              void* d_out, int out_size)
{
    const float4* x = (const float4*)d_in[0];
    const float*  w = (const float*)d_in[1];   // [3,1024,1]
    const float*  b = (const float*)d_in[2];   // [3,1024,1]
    float4* out = (float4*)d_out;

    const int n_rows = in_sizes[0] / F_DIM;    // 16384
    const int warps_per_block = 8;             // 256 threads
    const int rows_per_block = warps_per_block;
    const int grid = (n_rows + rows_per_block - 1) / rows_per_block;

    cross_layer_kernel<<<grid, 256>>>(x, w, b, out, n_rows);
}

// round 3
// speedup vs baseline: 1.8887x; 1.8887x over previous
#include <cuda_runtime.h>

// DCN CrossLayer, restructured:
//   xl3 = x0 * a3 + (b0+b1+b2)
// where a3 derives from d_l = dot(x0,w_l) and precomputed scalars
//   c1 = dot(b0, w1), c2 = dot(b0+b1, w2):
//   a1 = 1+d0; s1 = a1*d1+c1; a2 = a1+s1; s2 = a2*d2+c2; a3 = a2+s2.
// Exact identity (in real arithmetic) with the reference recurrence.
//
// w0..w2 and B = b0+b1+b2 staged in shared per block; c1,c2 computed in a
// per-block prologue (12 KB L2-hot reads). Global traffic = x once + out once.

#define F_DIM 1024
#define F4    (F_DIM / 4)   // 256 float4 per row
#define VEC   8             // float4 per lane (256 / 32)

__device__ __forceinline__ float dot4(float4 a, float4 b, float acc) {
    acc = fmaf(a.x, b.x, acc);
    acc = fmaf(a.y, b.y, acc);
    acc = fmaf(a.z, b.z, acc);
    return fmaf(a.w, b.w, acc);
}

__global__ void __launch_bounds__(256, 4)
cross_layer_kernel(const float4* __restrict__ x,
                   const float*  __restrict__ w,   // [3,1024]
                   const float*  __restrict__ b,   // [3,1024]
                   float4* __restrict__ out,
                   int n_rows)
{
    __shared__ float4 sw0[F4], sw1[F4], sw2[F4], sB[F4];
    __shared__ float  sred[16];

    const int tid  = threadIdx.x;
    const int lane = tid & 31;
    const int wid  = tid >> 5;
    const int row  = blockIdx.x * 8 + wid;

    // ---- Prologue: stage w0,w1,w2,B into smem; block-reduce c1,c2 ----
    {
        const float4* w0g = (const float4*)(w);
        const float4* w1g = (const float4*)(w + F_DIM);
        const float4* w2g = (const float4*)(w + 2 * F_DIM);
        const float4* b0g = (const float4*)(b);
        const float4* b1g = (const float4*)(b + F_DIM);
        const float4* b2g = (const float4*)(b + 2 * F_DIM);

        float4 w1v = __ldg(&w1g[tid]);
        float4 w2v = __ldg(&w2g[tid]);
        float4 b0v = __ldg(&b0g[tid]);
        float4 b1v = __ldg(&b1g[tid]);
        float4 b2v = __ldg(&b2g[tid]);
        sw0[tid] = __ldg(&w0g[tid]);
        sw1[tid] = w1v;
        sw2[tid] = w2v;

        float4 b01, Bv;
        b01.x = b0v.x + b1v.x;  b01.y = b0v.y + b1v.y;
        b01.z = b0v.z + b1v.z;  b01.w = b0v.w + b1v.w;
        Bv.x = b01.x + b2v.x;   Bv.y = b01.y + b2v.y;
        Bv.z = b01.z + b2v.z;   Bv.w = b01.w + b2v.w;
        sB[tid] = Bv;

        float c1p = dot4(b0v, w1v, 0.0f);
        float c2p = dot4(b01, w2v, 0.0f);
#pragma unroll
        for (int o = 16; o; o >>= 1) {
            c1p += __shfl_xor_sync(0xffffffffu, c1p, o);
            c2p += __shfl_xor_sync(0xffffffffu, c2p, o);
        }
        if (lane == 0) { sred[wid] = c1p; sred[8 + wid] = c2p; }
    }
    __syncthreads();

    float c1 = 0.0f, c2 = 0.0f;
#pragma unroll
    for (int i = 0; i < 8; i++) { c1 += sred[i]; c2 += sred[8 + i]; }

    if (row >= n_rows) return;

    // ---- Load x0 (front-batched, coalesced) ----
    const float4* __restrict__ xrow = x + (size_t)row * F4;
    float4 x0[VEC];
#pragma unroll
    for (int i = 0; i < VEC; i++)
        x0[i] = __ldg(&xrow[i * 32 + lane]);

    // ---- Three dots of x0 against w0,w1,w2 (w from smem) ----
    float d0 = 0.0f, d1 = 0.0f, d2 = 0.0f;
#pragma unroll
    for (int i = 0; i < VEC; i++) {
        const int idx = i * 32 + lane;
        d0 = dot4(x0[i], sw0[idx], d0);
        d1 = dot4(x0[i], sw1[idx], d1);
        d2 = dot4(x0[i], sw2[idx], d2);
    }
#pragma unroll
    for (int o = 16; o; o >>= 1) {
        d0 += __shfl_xor_sync(0xffffffffu, d0, o);
        d1 += __shfl_xor_sync(0xffffffffu, d1, o);
        d2 += __shfl_xor_sync(0xffffffffu, d2, o);
    }

    const float a1 = 1.0f + d0;
    const float s1 = fmaf(a1, d1, c1);
    const float a2 = a1 + s1;
    const float s2 = fmaf(a2, d2, c2);
    const float a3 = a2 + s2;

    // ---- out = x0 * a3 + B ----
    float4* __restrict__ orow = out + (size_t)row * F4;
#pragma unroll
    for (int i = 0; i < VEC; i++) {
        const int idx = i * 32 + lane;
        float4 Bq = sB[idx];
        float4 o;
        o.x = fmaf(x0[i].x, a3, Bq.x);
        o.y = fmaf(x0[i].y, a3, Bq.y);
        o.z = fmaf(x0[i].z, a3, Bq.z);
        o.w = fmaf(x0[i].w, a3, Bq.w);
        orow[idx] = o;
    }
}

extern "C" void kernel_launch(void* const* d_in, const int* in_sizes, int n_in,
                              void* d_out, int out_size)
{
    const float4* x = (const float4*)d_in[0];
    const float*  w = (const float*)d_in[1];   // [3,1024,1]
    const float*  b = (const float*)d_in[2];   // [3,1024,1]
    float4* out = (float4*)d_out;

    const int n_rows = in_sizes[0] / F_DIM;            // 16384
    const int grid   = (n_rows + 7) / 8;               // 8 rows (warps) per block

    cross_layer_kernel<<<grid, 256>>>(x, w, b, out, n_rows);
}